// round 1
// baseline (speedup 1.0000x reference)
#include <cuda_runtime.h>
#include <cuda_bf16.h>

// ChannelAttentionModule: out = x + (F @ softmax(F^T F, axis=-1)^T) with F = x.reshape(B,C,N)
// B=8, C=64, N=H*W=4096, fp32. Flash-attention style, fp32 FFMA baseline.

constexpr int C    = 64;
constexpr int NPOS = 4096;
constexpr int BM   = 128;   // query rows per CTA
constexpr int BN   = 64;    // key cols per tile
constexpr int KT_STRIDE = 65; // padded to kill bank conflicts on transposed K

// shared memory layout (floats)
constexpr int SM_QS = 0;                        // Qs[64][128]  (channel-major slice of F)
constexpr int SM_KS = SM_QS + C * BM;           // Ks[64][64]
constexpr int SM_KT = SM_KS + C * BN;           // Kt[64][65]   (transposed K, padded)
constexpr int SM_PS = SM_KT + BN * KT_STRIDE;   // Ps[128][64]
constexpr int SMEM_FLOATS = SM_PS + BM * BN;
constexpr int SMEM_BYTES  = SMEM_FLOATS * 4;    // 98560 B per CTA

__global__ __launch_bounds__(256, 2)
void attn_flash_fp32_kernel(const float* __restrict__ x, float* __restrict__ out)
{
    extern __shared__ float sm[];
    float* Qs = sm + SM_QS;
    float* Ks = sm + SM_KS;
    float* Kt = sm + SM_KT;
    float* Ps = sm + SM_PS;

    const int b  = blockIdx.y;
    const int m0 = blockIdx.x * BM;
    const float* xb = x + (size_t)b * C * NPOS;

    const int tid = threadIdx.x;
    const int tm  = tid >> 4;   // 0..15 -> rows m = tm*8 .. tm*8+7
    const int tn  = tid & 15;   // 0..15 -> cols n = tn*4 .. +3 ; channels c = tn*4 .. +3

    // ---- Load Q tile: Qs[c][m] = x[b, c, m0+m] ------------------------------
    #pragma unroll
    for (int idx = tid; idx < C * (BM / 4); idx += 256) {
        int c = idx >> 5;          // BM/4 = 32 float4 per channel row
        int v = idx & 31;
        float4 g = *(const float4*)(xb + (size_t)c * NPOS + m0 + v * 4);
        *(float4*)(Qs + c * BM + v * 4) = g;
    }

    float Mx[8], l[8], O[8][4];
    #pragma unroll
    for (int i = 0; i < 8; ++i) {
        Mx[i] = -1e30f; l[i] = 0.f;
        #pragma unroll
        for (int j = 0; j < 4; ++j) O[i][j] = 0.f;
    }

    const float LOG2E = 1.4426950408889634f;

    for (int j = 0; j < NPOS / BN; ++j) {
        const int n0 = j * BN;

        __syncthreads();   // previous iteration done reading Ks/Kt/Ps

        // ---- Load K tile: Ks[c][n] and transposed Kt[n][c] ------------------
        #pragma unroll
        for (int idx = tid; idx < C * (BN / 4); idx += 256) {
            int c = idx >> 4;       // BN/4 = 16 float4 per channel row
            int v = idx & 15;
            float4 g = *(const float4*)(xb + (size_t)c * NPOS + n0 + v * 4);
            *(float4*)(Ks + c * BN + v * 4) = g;
            Kt[(v * 4 + 0) * KT_STRIDE + c] = g.x;
            Kt[(v * 4 + 1) * KT_STRIDE + c] = g.y;
            Kt[(v * 4 + 2) * KT_STRIDE + c] = g.z;
            Kt[(v * 4 + 3) * KT_STRIDE + c] = g.w;
        }
        __syncthreads();

        // ---- S[m][n] = sum_c Qs[c][m] * Ks[c][n] ---------------------------
        float S[8][4];
        #pragma unroll
        for (int i = 0; i < 8; ++i)
            #pragma unroll
            for (int k = 0; k < 4; ++k) S[i][k] = 0.f;

        #pragma unroll 4
        for (int c = 0; c < C; ++c) {
            float4 k4 = *(const float4*)(Ks + c * BN + tn * 4);
            float4 qa = *(const float4*)(Qs + c * BM + tm * 8);
            float4 qb = *(const float4*)(Qs + c * BM + tm * 8 + 4);
            float q[8] = {qa.x, qa.y, qa.z, qa.w, qb.x, qb.y, qb.z, qb.w};
            float kk[4] = {k4.x, k4.y, k4.z, k4.w};
            #pragma unroll
            for (int i = 0; i < 8; ++i)
                #pragma unroll
                for (int k = 0; k < 4; ++k)
                    S[i][k] = fmaf(q[i], kk[k], S[i][k]);
        }

        // ---- online softmax per row, write P to smem -----------------------
        #pragma unroll
        for (int i = 0; i < 8; ++i) {
            float mx = fmaxf(fmaxf(S[i][0], S[i][1]), fmaxf(S[i][2], S[i][3]));
            #pragma unroll
            for (int o = 8; o >= 1; o >>= 1)
                mx = fmaxf(mx, __shfl_xor_sync(0xffffffffu, mx, o));
            float Mn = fmaxf(Mx[i], mx);
            float scale = __expf(Mx[i] - Mn);    // exp(old_max - new_max)
            float p[4], ssum = 0.f;
            #pragma unroll
            for (int k = 0; k < 4; ++k) {
                p[k] = exp2f((S[i][k] - Mn) * LOG2E);
                ssum += p[k];
            }
            #pragma unroll
            for (int o = 8; o >= 1; o >>= 1)
                ssum += __shfl_xor_sync(0xffffffffu, ssum, o);
            l[i]  = l[i] * scale + ssum;
            Mx[i] = Mn;
            #pragma unroll
            for (int k = 0; k < 4; ++k) O[i][k] *= scale;
            *(float4*)(Ps + (tm * 8 + i) * BN + tn * 4) =
                make_float4(p[0], p[1], p[2], p[3]);
        }
        __syncthreads();   // P tile visible to everyone

        // ---- O[m][c] += sum_n Ps[m][n] * Kt[n][c] --------------------------
        #pragma unroll 2
        for (int n4 = 0; n4 < BN / 4; ++n4) {
            float kt[4][4];
            #pragma unroll
            for (int r = 0; r < 4; ++r)
                #pragma unroll
                for (int cc = 0; cc < 4; ++cc)
                    kt[r][cc] = Kt[(n4 * 4 + r) * KT_STRIDE + tn * 4 + cc];
            #pragma unroll
            for (int i = 0; i < 8; ++i) {
                float4 p4 = *(const float4*)(Ps + (tm * 8 + i) * BN + n4 * 4);
                float p[4] = {p4.x, p4.y, p4.z, p4.w};
                #pragma unroll
                for (int r = 0; r < 4; ++r)
                    #pragma unroll
                    for (int cc = 0; cc < 4; ++cc)
                        O[i][cc] = fmaf(p[r], kt[r][cc], O[i][cc]);
            }
        }
    }

    // ---- epilogue: out = x + O / l  (residual read from resident Q tile) ----
    float* outb = out + (size_t)b * C * NPOS;
    #pragma unroll
    for (int i = 0; i < 8; ++i) {
        float inv = 1.0f / l[i];
        int m = tm * 8 + i;
        #pragma unroll
        for (int cc = 0; cc < 4; ++cc) {
            int c = tn * 4 + cc;
            outb[(size_t)c * NPOS + m0 + m] = Qs[c * BM + m] + O[i][cc] * inv;
        }
    }
}

extern "C" void kernel_launch(void* const* d_in, const int* in_sizes, int n_in,
                              void* d_out, int out_size)
{
    const float* x = (const float*)d_in[0];
    float* out = (float*)d_out;
    const int B = in_sizes[0] / (C * NPOS);   // 8

    cudaFuncSetAttribute(attn_flash_fp32_kernel,
                         cudaFuncAttributeMaxDynamicSharedMemorySize, SMEM_BYTES);

    dim3 grid(NPOS / BM, B);
    attn_flash_fp32_kernel<<<grid, 256, SMEM_BYTES>>>(x, out);
}